// round 1
// baseline (speedup 1.0000x reference)
#include <cuda_runtime.h>
#include <math.h>

#define NMAX 100000
#define HID  64
#define MHID 128
#define KOUT 15

// ---- device-global scratch (no allocations allowed) ----
__device__ float g_a[NMAX * HID];    // hw (pre-scaled by dis[src])
__device__ float g_b[NMAX * HID];    // aggregation accumulator / pre-activation
__device__ float g_m[NMAX * MHID];   // MLP hidden
__device__ float g_dis[NMAX];        // deg^{-1/2}
__device__ int   g_deg[NMAX];

__device__ __forceinline__ float eluf(float v) { return v > 0.f ? v : expm1f(v); }

// ---------------------------------------------------------------- degrees
__global__ void k_deg_init(int n) {
    int i = blockIdx.x * blockDim.x + threadIdx.x;
    if (i < n) g_deg[i] = 1;                       // self-loop
}
__global__ void k_deg_edge(const int* __restrict__ ei, int E) {
    int e = blockIdx.x * blockDim.x + threadIdx.x;
    if (e < E) atomicAdd(&g_deg[ei[E + e]], 1);    // dst row
}
__global__ void k_dis(int n) {
    int i = blockIdx.x * blockDim.x + threadIdx.x;
    if (i < n) g_dis[i] = rsqrtf((float)g_deg[i]);
}

// ------------------------------------------- layer-1 input GEMM (3 -> 64)
// g_a[i,f] = (x[i] @ W1)[f] * dis[i]          (pre-scaled messages)
// g_b[i,f] = g_a[i,f] * dis[i]                (self-loop term = output init)
__global__ void k_hw1(const float* __restrict__ x, const float* __restrict__ W1, int n) {
    int idx = blockIdx.x * blockDim.x + threadIdx.x;
    if (idx >= n * HID) return;
    int i = idx >> 6, f = idx & 63;
    float d = g_dis[i];
    float v = x[i * 3 + 0] * W1[f]
            + x[i * 3 + 1] * W1[HID + f]
            + x[i * 3 + 2] * W1[2 * HID + f];
    v *= d;
    g_a[idx] = v;
    g_b[idx] = v * d;
}

// ------------------------------------------------- edge propagation (hot)
// warp per edge; lane handles 2 features (float2 gather, 2 coalesced REDs)
__global__ void k_edge(const int* __restrict__ ei, int E) {
    int t = blockIdx.x * blockDim.x + threadIdx.x;
    int e = t >> 5;
    if (e >= E) return;
    int lane = t & 31;
    int s = ei[e];
    int d = ei[E + e];
    float nd = g_dis[d];
    const float2* hws = reinterpret_cast<const float2*>(g_a);
    float2 v = hws[s * 32 + lane];
    atomicAdd(&g_b[d * HID + 2 * lane + 0], v.x * nd);
    atomicAdd(&g_b[d * HID + 2 * lane + 1], v.y * nd);
}

// ---------------------------------------- layer-2 GEMM: elu(g_b+b1) @ W2
// reads g_b rows -> smem, writes g_a = result*dis, g_b = result*dis*dis
__global__ void k_gcn_gemm64(const float* __restrict__ bias,
                             const float* __restrict__ W, int n) {
    __shared__ float As[32][HID];
    __shared__ float Ws[HID * HID];
    int tid = threadIdx.x;
    int row0 = blockIdx.x * 32;

    for (int i = tid; i < HID * HID; i += 256) Ws[i] = W[i];
    for (int i = tid; i < 32 * HID; i += 256) {
        int r = i >> 6, k = i & 63;
        int row = row0 + r;
        As[r][k] = (row < n) ? eluf(g_b[row * HID + k] + bias[k]) : 0.f;
    }
    __syncthreads();

    int fx = (tid & 15) * 4;
    int n0 = (tid >> 4) * 2;
    float4 a0c = make_float4(0.f, 0.f, 0.f, 0.f);
    float4 a1c = make_float4(0.f, 0.f, 0.f, 0.f);
#pragma unroll 16
    for (int k = 0; k < HID; k++) {
        float4 w = *reinterpret_cast<const float4*>(&Ws[k * HID + fx]);
        float a0 = As[n0][k], a1 = As[n0 + 1][k];
        a0c.x += a0 * w.x; a0c.y += a0 * w.y; a0c.z += a0 * w.z; a0c.w += a0 * w.w;
        a1c.x += a1 * w.x; a1c.y += a1 * w.y; a1c.z += a1 * w.z; a1c.w += a1 * w.w;
    }
#pragma unroll
    for (int r = 0; r < 2; r++) {
        int row = row0 + n0 + r;
        if (row >= n) continue;
        float d = g_dis[row];
        float4 acc = r ? a1c : a0c;
        float4 h = make_float4(acc.x * d, acc.y * d, acc.z * d, acc.w * d);
        *reinterpret_cast<float4*>(&g_a[row * HID + fx]) = h;
        float4 o = make_float4(h.x * d, h.y * d, h.z * d, h.w * d);
        *reinterpret_cast<float4*>(&g_b[row * HID + fx]) = o;
    }
}

// -------------------------------- MLP layer 1: elu(elu(g_b+b2) @ Wm1 + bm1)
__global__ void k_mlp1(const float* __restrict__ b2,
                       const float* __restrict__ Wm1,
                       const float* __restrict__ bm1, int n) {
    __shared__ float As[16][HID];
    __shared__ float Ws[HID * MHID];
    int tid = threadIdx.x;
    int row0 = blockIdx.x * 16;

    for (int i = tid; i < HID * MHID; i += 256) Ws[i] = Wm1[i];
    for (int i = tid; i < 16 * HID; i += 256) {
        int r = i >> 6, k = i & 63;
        int row = row0 + r;
        As[r][k] = (row < n) ? eluf(g_b[row * HID + k] + b2[k]) : 0.f;
    }
    __syncthreads();

    int fx = (tid & 31) * 4;
    int n0 = (tid >> 5) * 2;
    float4 a0c = make_float4(0.f, 0.f, 0.f, 0.f);
    float4 a1c = make_float4(0.f, 0.f, 0.f, 0.f);
#pragma unroll 16
    for (int k = 0; k < HID; k++) {
        float4 w = *reinterpret_cast<const float4*>(&Ws[k * MHID + fx]);
        float a0 = As[n0][k], a1 = As[n0 + 1][k];
        a0c.x += a0 * w.x; a0c.y += a0 * w.y; a0c.z += a0 * w.z; a0c.w += a0 * w.w;
        a1c.x += a1 * w.x; a1c.y += a1 * w.y; a1c.z += a1 * w.z; a1c.w += a1 * w.w;
    }
    float4 bb = *reinterpret_cast<const float4*>(&bm1[fx]);
#pragma unroll
    for (int r = 0; r < 2; r++) {
        int row = row0 + n0 + r;
        if (row >= n) continue;
        float4 acc = r ? a1c : a0c;
        float4 o = make_float4(eluf(acc.x + bb.x), eluf(acc.y + bb.y),
                               eluf(acc.z + bb.z), eluf(acc.w + bb.w));
        *reinterpret_cast<float4*>(&g_m[row * MHID + fx]) = o;
    }
}

// ------------------------ MLP layer 2 + softmax, warp per node (K = 15)
__global__ void k_mlp2(const float* __restrict__ Wm2,
                       const float* __restrict__ bm2,
                       float* __restrict__ out, int n) {
    int gw = (blockIdx.x * blockDim.x + threadIdx.x) >> 5;
    int lane = threadIdx.x & 31;
    if (gw >= n) return;
    const float* mr = g_m + (size_t)gw * MHID;

    float p[KOUT];
#pragma unroll
    for (int c = 0; c < KOUT; c++) p[c] = 0.f;
#pragma unroll
    for (int j = 0; j < 4; j++) {
        int k = lane + 32 * j;
        float mv = mr[k];
        const float* wr = Wm2 + k * KOUT;
#pragma unroll
        for (int c = 0; c < KOUT; c++) p[c] += mv * __ldg(&wr[c]);
    }
#pragma unroll
    for (int off = 16; off > 0; off >>= 1)
#pragma unroll
        for (int c = 0; c < KOUT; c++)
            p[c] += __shfl_xor_sync(0xffffffffu, p[c], off);

    float mx = -1e30f;
#pragma unroll
    for (int c = 0; c < KOUT; c++) { p[c] += bm2[c]; mx = fmaxf(mx, p[c]); }
    float s = 0.f;
#pragma unroll
    for (int c = 0; c < KOUT; c++) { p[c] = expf(p[c] - mx); s += p[c]; }
    float inv = 1.f / s;
#pragma unroll
    for (int c = 0; c < KOUT; c++)
        if (lane == c) out[gw * KOUT + c] = p[c] * inv;
}

// ---------------------------------------------------------------- launch
extern "C" void kernel_launch(void* const* d_in, const int* in_sizes, int n_in,
                              void* d_out, int out_size) {
    const float* x   = (const float*)d_in[0];
    const int*   ei  = (const int*)  d_in[1];
    const float* W1  = (const float*)d_in[2];
    const float* b1  = (const float*)d_in[3];
    const float* W2  = (const float*)d_in[4];
    const float* b2  = (const float*)d_in[5];
    const float* Wm1 = (const float*)d_in[6];
    const float* bm1 = (const float*)d_in[7];
    const float* Wm2 = (const float*)d_in[8];
    const float* bm2 = (const float*)d_in[9];
    float* out = (float*)d_out;

    int n = in_sizes[0] / 3;
    int E = in_sizes[1] / 2;

    k_deg_init<<<(n + 255) / 256, 256>>>(n);
    k_deg_edge<<<(E + 255) / 256, 256>>>(ei, E);
    k_dis<<<(n + 255) / 256, 256>>>(n);

    // layer 1
    k_hw1<<<(n * HID + 255) / 256, 256>>>(x, W1, n);
    int edge_blocks = (int)(((long long)E * 32 + 255) / 256);
    k_edge<<<edge_blocks, 256>>>(ei, E);

    // layer 2
    k_gcn_gemm64<<<(n + 31) / 32, 256>>>(b1, W2, n);
    k_edge<<<edge_blocks, 256>>>(ei, E);

    // MLP + softmax
    k_mlp1<<<(n + 15) / 16, 256>>>(b2, Wm1, bm1, n);
    k_mlp2<<<(n * 32 + 255) / 256, 256>>>(Wm2, bm2, out, n);
}

// round 2
// speedup vs baseline: 2.1028x; 2.1028x over previous
#include <cuda_runtime.h>
#include <math.h>

#define NMAX 100000
#define EMAX 3200000
#define HID  64
#define MHID 128
#define KOUT 15
#define SCAN_BS 1024

// ---- device-global scratch (no allocations allowed) ----
__device__ float g_a[NMAX * HID];    // pre-scaled messages (hw * dis[src])
__device__ float g_b[NMAX * HID];    // aggregated output / GEMM input
__device__ float g_m[NMAX * MHID];   // MLP hidden
__device__ float g_dis[NMAX];        // (deg+1)^{-1/2}
__device__ int   g_deg[NMAX];        // in-degree (excl. self loop)
__device__ int   g_off[NMAX + 1];    // CSR row offsets
__device__ int   g_cur[NMAX];        // scatter cursors
__device__ int   g_csr[EMAX];        // CSR src indices
__device__ int   g_bsum[(NMAX + SCAN_BS - 1) / SCAN_BS];
__device__ int   g_boff[(NMAX + SCAN_BS - 1) / SCAN_BS];

__device__ __forceinline__ float eluf(float v) { return v > 0.f ? v : expm1f(v); }

// ---------------------------------------------------------------- degrees
__global__ void k_deg_init(int n) {
    int i = blockIdx.x * blockDim.x + threadIdx.x;
    if (i < n) g_deg[i] = 0;
}
__global__ void k_deg_edge(const int* __restrict__ ei, int E) {
    int e = blockIdx.x * blockDim.x + threadIdx.x;
    if (e < E) atomicAdd(&g_deg[ei[E + e]], 1);
}

// ----------------------------------------------------- exclusive scan (3x)
__global__ void k_scan1(int n) {
    __shared__ int s[SCAN_BS];
    int t = threadIdx.x;
    int i = blockIdx.x * SCAN_BS + t;
    int v = (i < n) ? g_deg[i] : 0;
    s[t] = v;
    __syncthreads();
#pragma unroll
    for (int off = 1; off < SCAN_BS; off <<= 1) {
        int add = (t >= off) ? s[t - off] : 0;
        __syncthreads();
        s[t] += add;
        __syncthreads();
    }
    if (i < n) g_off[i] = s[t] - v;            // intra-block exclusive
    if (t == SCAN_BS - 1) g_bsum[blockIdx.x] = s[t];
}
__global__ void k_scan2(int nb) {
    __shared__ int s[128];
    int t = threadIdx.x;
    int v = (t < nb) ? g_bsum[t] : 0;
    s[t] = v;
    __syncthreads();
#pragma unroll
    for (int off = 1; off < 128; off <<= 1) {
        int add = (t >= off) ? s[t - off] : 0;
        __syncthreads();
        s[t] += add;
        __syncthreads();
    }
    if (t < nb) g_boff[t] = s[t] - v;
}
__global__ void k_scan3(int n, int E) {
    int i = blockIdx.x * blockDim.x + threadIdx.x;
    if (i < n) {
        int off = g_off[i] + g_boff[i >> 10];
        g_off[i] = off;
        g_cur[i] = off;
        g_dis[i] = rsqrtf((float)(g_deg[i] + 1));   // +1 self loop
    }
    if (i == 0) g_off[n] = E;
}

// -------------------------------------------------------------- scatter
__global__ void k_scatter(const int* __restrict__ ei, int E) {
    int e = blockIdx.x * blockDim.x + threadIdx.x;
    if (e < E) {
        int s = ei[e];
        int d = ei[E + e];
        int p = atomicAdd(&g_cur[d], 1);
        g_csr[p] = s;
    }
}

// ------------------------------------------- layer-1 input GEMM (3 -> 64)
__global__ void k_hw1(const float* __restrict__ x, const float* __restrict__ W1, int n) {
    int idx = blockIdx.x * blockDim.x + threadIdx.x;
    if (idx >= n * HID) return;
    int i = idx >> 6, f = idx & 63;
    float v = x[i * 3 + 0] * W1[f]
            + x[i * 3 + 1] * W1[HID + f]
            + x[i * 3 + 2] * W1[2 * HID + f];
    g_a[idx] = v * g_dis[i];                      // pre-scaled message
}

// --------------------------------------------- CSR aggregation (hot, x2)
// warp per node; lane holds 2 features; accumulator init = self message
__global__ void k_aggr(int n) {
    int gw = (blockIdx.x * blockDim.x + threadIdx.x) >> 5;
    if (gw >= n) return;
    int lane = threadIdx.x & 31;
    const float2* a2 = reinterpret_cast<const float2*>(g_a);

    float2 acc = a2[gw * 32 + lane];              // self loop
    int j = g_off[gw];
    int end = g_off[gw + 1];
    for (; j + 4 <= end; j += 4) {
        int s0 = g_csr[j], s1 = g_csr[j + 1], s2 = g_csr[j + 2], s3 = g_csr[j + 3];
        float2 v0 = a2[s0 * 32 + lane];
        float2 v1 = a2[s1 * 32 + lane];
        float2 v2 = a2[s2 * 32 + lane];
        float2 v3 = a2[s3 * 32 + lane];
        acc.x += (v0.x + v1.x) + (v2.x + v3.x);
        acc.y += (v0.y + v1.y) + (v2.y + v3.y);
    }
    for (; j < end; j++) {
        int s = g_csr[j];
        float2 v = a2[s * 32 + lane];
        acc.x += v.x;
        acc.y += v.y;
    }
    float d = g_dis[gw];
    float2 o = make_float2(acc.x * d, acc.y * d);
    reinterpret_cast<float2*>(g_b)[gw * 32 + lane] = o;
}

// ---------------------------------------- layer-2 GEMM: elu(g_b+b1) @ W2
__global__ void k_gcn_gemm64(const float* __restrict__ bias,
                             const float* __restrict__ W, int n) {
    __shared__ float As[32][HID];
    __shared__ float Ws[HID * HID];
    int tid = threadIdx.x;
    int row0 = blockIdx.x * 32;

    for (int i = tid; i < HID * HID; i += 256) Ws[i] = W[i];
    for (int i = tid; i < 32 * HID; i += 256) {
        int r = i >> 6, k = i & 63;
        int row = row0 + r;
        As[r][k] = (row < n) ? eluf(g_b[row * HID + k] + bias[k]) : 0.f;
    }
    __syncthreads();

    int fx = (tid & 15) * 4;
    int n0 = (tid >> 4) * 2;
    float4 a0c = make_float4(0.f, 0.f, 0.f, 0.f);
    float4 a1c = make_float4(0.f, 0.f, 0.f, 0.f);
#pragma unroll 16
    for (int k = 0; k < HID; k++) {
        float4 w = *reinterpret_cast<const float4*>(&Ws[k * HID + fx]);
        float a0 = As[n0][k], a1 = As[n0 + 1][k];
        a0c.x += a0 * w.x; a0c.y += a0 * w.y; a0c.z += a0 * w.z; a0c.w += a0 * w.w;
        a1c.x += a1 * w.x; a1c.y += a1 * w.y; a1c.z += a1 * w.z; a1c.w += a1 * w.w;
    }
#pragma unroll
    for (int r = 0; r < 2; r++) {
        int row = row0 + n0 + r;
        if (row >= n) continue;
        float d = g_dis[row];
        float4 acc = r ? a1c : a0c;
        float4 h = make_float4(acc.x * d, acc.y * d, acc.z * d, acc.w * d);
        *reinterpret_cast<float4*>(&g_a[row * HID + fx]) = h;   // pre-scaled msg
    }
}

// -------------------------------- MLP layer 1: elu(elu(g_b+b2) @ Wm1 + bm1)
__global__ void k_mlp1(const float* __restrict__ b2,
                       const float* __restrict__ Wm1,
                       const float* __restrict__ bm1, int n) {
    __shared__ float As[16][HID];
    __shared__ float Ws[HID * MHID];
    int tid = threadIdx.x;
    int row0 = blockIdx.x * 16;

    for (int i = tid; i < HID * MHID; i += 256) Ws[i] = Wm1[i];
    for (int i = tid; i < 16 * HID; i += 256) {
        int r = i >> 6, k = i & 63;
        int row = row0 + r;
        As[r][k] = (row < n) ? eluf(g_b[row * HID + k] + b2[k]) : 0.f;
    }
    __syncthreads();

    int fx = (tid & 31) * 4;
    int n0 = (tid >> 5) * 2;
    float4 a0c = make_float4(0.f, 0.f, 0.f, 0.f);
    float4 a1c = make_float4(0.f, 0.f, 0.f, 0.f);
#pragma unroll 16
    for (int k = 0; k < HID; k++) {
        float4 w = *reinterpret_cast<const float4*>(&Ws[k * MHID + fx]);
        float a0 = As[n0][k], a1 = As[n0 + 1][k];
        a0c.x += a0 * w.x; a0c.y += a0 * w.y; a0c.z += a0 * w.z; a0c.w += a0 * w.w;
        a1c.x += a1 * w.x; a1c.y += a1 * w.y; a1c.z += a1 * w.z; a1c.w += a1 * w.w;
    }
    float4 bb = *reinterpret_cast<const float4*>(&bm1[fx]);
#pragma unroll
    for (int r = 0; r < 2; r++) {
        int row = row0 + n0 + r;
        if (row >= n) continue;
        float4 acc = r ? a1c : a0c;
        float4 o = make_float4(eluf(acc.x + bb.x), eluf(acc.y + bb.y),
                               eluf(acc.z + bb.z), eluf(acc.w + bb.w));
        *reinterpret_cast<float4*>(&g_m[row * MHID + fx]) = o;
    }
}

// ------------------------ MLP layer 2 + softmax, warp per node (K = 15)
__global__ void k_mlp2(const float* __restrict__ Wm2,
                       const float* __restrict__ bm2,
                       float* __restrict__ out, int n) {
    int gw = (blockIdx.x * blockDim.x + threadIdx.x) >> 5;
    int lane = threadIdx.x & 31;
    if (gw >= n) return;
    const float* mr = g_m + (size_t)gw * MHID;

    float p[KOUT];
#pragma unroll
    for (int c = 0; c < KOUT; c++) p[c] = 0.f;
#pragma unroll
    for (int j = 0; j < 4; j++) {
        int k = lane + 32 * j;
        float mv = mr[k];
        const float* wr = Wm2 + k * KOUT;
#pragma unroll
        for (int c = 0; c < KOUT; c++) p[c] += mv * __ldg(&wr[c]);
    }
#pragma unroll
    for (int off = 16; off > 0; off >>= 1)
#pragma unroll
        for (int c = 0; c < KOUT; c++)
            p[c] += __shfl_xor_sync(0xffffffffu, p[c], off);

    float mx = -1e30f;
#pragma unroll
    for (int c = 0; c < KOUT; c++) { p[c] += bm2[c]; mx = fmaxf(mx, p[c]); }
    float s = 0.f;
#pragma unroll
    for (int c = 0; c < KOUT; c++) { p[c] = expf(p[c] - mx); s += p[c]; }
    float inv = 1.f / s;
#pragma unroll
    for (int c = 0; c < KOUT; c++)
        if (lane == c) out[gw * KOUT + c] = p[c] * inv;
}

// ---------------------------------------------------------------- launch
extern "C" void kernel_launch(void* const* d_in, const int* in_sizes, int n_in,
                              void* d_out, int out_size) {
    const float* x   = (const float*)d_in[0];
    const int*   ei  = (const int*)  d_in[1];
    const float* W1  = (const float*)d_in[2];
    const float* b1  = (const float*)d_in[3];
    const float* W2  = (const float*)d_in[4];
    const float* b2  = (const float*)d_in[5];
    const float* Wm1 = (const float*)d_in[6];
    const float* bm1 = (const float*)d_in[7];
    const float* Wm2 = (const float*)d_in[8];
    const float* bm2 = (const float*)d_in[9];
    float* out = (float*)d_out;

    int n = in_sizes[0] / 3;
    int E = in_sizes[1] / 2;
    int nb = (n + SCAN_BS - 1) / SCAN_BS;

    // CSR build
    k_deg_init<<<(n + 255) / 256, 256>>>(n);
    k_deg_edge<<<(E + 255) / 256, 256>>>(ei, E);
    k_scan1<<<nb, SCAN_BS>>>(n);
    k_scan2<<<1, 128>>>(nb);
    k_scan3<<<(n + 255) / 256, 256>>>(n, E);
    k_scatter<<<(E + 255) / 256, 256>>>(ei, E);

    // layer 1
    k_hw1<<<(n * HID + 255) / 256, 256>>>(x, W1, n);
    int aggr_blocks = (n * 32 + 255) / 256;
    k_aggr<<<aggr_blocks, 256>>>(n);

    // layer 2
    k_gcn_gemm64<<<(n + 31) / 32, 256>>>(b1, W2, n);
    k_aggr<<<aggr_blocks, 256>>>(n);

    // MLP + softmax
    k_mlp1<<<(n + 15) / 16, 256>>>(b2, Wm1, bm1, n);
    k_mlp2<<<(n * 32 + 255) / 256, 256>>>(Wm2, bm2, out, n);
}

// round 3
// speedup vs baseline: 2.2461x; 1.0681x over previous
#include <cuda_runtime.h>
#include <math.h>

#define NMAX 100000
#define EMAX 3200000
#define CSRMAX (EMAX + 3 * NMAX + 8)
#define HID  64
#define MHID 128
#define KOUT 15
#define SCAN_BS 1024

// ---- device-global scratch (no allocations allowed) ----
__device__ float g_a[(NMAX + 1) * HID];  // pre-scaled messages; row n = zeros (dummy)
__device__ float g_b[NMAX * HID];        // aggregated output / GEMM input
__device__ float g_dis[NMAX];            // (deg+1)^{-1/2}
__device__ int   g_deg[NMAX];            // in-degree (excl. self loop)
__device__ int   g_off[NMAX + 1];        // CSR row offsets (padded to x4)
__device__ int   g_cur[NMAX];            // scatter cursors
__device__ int   g_csr[CSRMAX];          // CSR src indices (padded with n)
__device__ int   g_bsum[(NMAX + SCAN_BS - 1) / SCAN_BS];
__device__ int   g_boff[(NMAX + SCAN_BS - 1) / SCAN_BS];

__device__ __forceinline__ float eluf(float v) { return v > 0.f ? v : expm1f(v); }

// ---------------------------------------------------------------- degrees
__global__ void k_deg_init(int n) {
    int i = blockIdx.x * blockDim.x + threadIdx.x;
    if (i < n) g_deg[i] = 0;
}
__global__ void k_deg_edge(const int* __restrict__ ei, int E) {
    int t = blockIdx.x * blockDim.x + threadIdx.x;
    int E4 = E >> 2;
    if (t < E4) {
        int4 d = reinterpret_cast<const int4*>(ei + E)[t];
        atomicAdd(&g_deg[d.x], 1);
        atomicAdd(&g_deg[d.y], 1);
        atomicAdd(&g_deg[d.z], 1);
        atomicAdd(&g_deg[d.w], 1);
    } else {
        int e = E4 * 4 + (t - E4);
        if (e < E) atomicAdd(&g_deg[ei[E + e]], 1);
    }
}

// ----------------------------------------------------- exclusive scan (3x) over padded degrees
__global__ void k_scan1(int n) {
    __shared__ int s[SCAN_BS];
    int t = threadIdx.x;
    int i = blockIdx.x * SCAN_BS + t;
    int v = (i < n) ? ((g_deg[i] + 3) & ~3) : 0;
    s[t] = v;
    __syncthreads();
#pragma unroll
    for (int off = 1; off < SCAN_BS; off <<= 1) {
        int add = (t >= off) ? s[t - off] : 0;
        __syncthreads();
        s[t] += add;
        __syncthreads();
    }
    if (i < n) g_off[i] = s[t] - v;
    if (t == SCAN_BS - 1) g_bsum[blockIdx.x] = s[t];
}
__global__ void k_scan2(int nb, int n) {
    __shared__ int s[128];
    int t = threadIdx.x;
    int v = (t < nb) ? g_bsum[t] : 0;
    s[t] = v;
    __syncthreads();
#pragma unroll
    for (int off = 1; off < 128; off <<= 1) {
        int add = (t >= off) ? s[t - off] : 0;
        __syncthreads();
        s[t] += add;
        __syncthreads();
    }
    if (t < nb) g_boff[t] = s[t] - v;
    if (t == 127) g_off[n] = s[127];      // padded total
}
// offsets finalize + dis + dummy-slot fill (slots [off+deg, off+pdeg))
__global__ void k_scan3(int n) {
    int i = blockIdx.x * blockDim.x + threadIdx.x;
    if (i >= n) return;
    int off = g_off[i] + g_boff[i >> 10];
    g_off[i] = off;
    g_cur[i] = off;
    int deg = g_deg[i];
    g_dis[i] = rsqrtf((float)(deg + 1));
    int pdeg = (deg + 3) & ~3;
    for (int j = deg; j < pdeg; j++) g_csr[off + j] = n;   // dummy -> zero row
}

// -------------------------------------------------------------- scatter
__global__ void k_scatter(const int* __restrict__ ei, int E) {
    int t = blockIdx.x * blockDim.x + threadIdx.x;
    int E4 = E >> 2;
    if (t < E4) {
        int4 s = reinterpret_cast<const int4*>(ei)[t];
        int4 d = reinterpret_cast<const int4*>(ei + E)[t];
        g_csr[atomicAdd(&g_cur[d.x], 1)] = s.x;
        g_csr[atomicAdd(&g_cur[d.y], 1)] = s.y;
        g_csr[atomicAdd(&g_cur[d.z], 1)] = s.z;
        g_csr[atomicAdd(&g_cur[d.w], 1)] = s.w;
    } else {
        int e = E4 * 4 + (t - E4);
        if (e < E) g_csr[atomicAdd(&g_cur[ei[E + e]], 1)] = ei[e];
    }
}

// ------------------------------------------- layer-1 input GEMM (3 -> 64)
__global__ void k_hw1(const float* __restrict__ x, const float* __restrict__ W1, int n) {
    int idx = blockIdx.x * blockDim.x + threadIdx.x;
    if (idx >= (n + 1) * HID) return;
    int i = idx >> 6, f = idx & 63;
    if (i == n) { g_a[idx] = 0.f; return; }       // dummy zero row
    float v = x[i * 3 + 0] * W1[f]
            + x[i * 3 + 1] * W1[HID + f]
            + x[i * 3 + 2] * W1[2 * HID + f];
    g_a[idx] = v * g_dis[i];
}

// --------------------------------------------- CSR aggregation (hot, x2)
// warp per node; lane holds 2 features; int4 index loads, 8 edges in flight
__global__ void k_aggr(int n) {
    int gw = (blockIdx.x * blockDim.x + threadIdx.x) >> 5;
    if (gw >= n) return;
    int lane = threadIdx.x & 31;
    const float2* __restrict__ a2 = reinterpret_cast<const float2*>(g_a);

    float2 acc = a2[gw * 32 + lane];              // self loop
    float2 acc2 = make_float2(0.f, 0.f);
    int j = g_off[gw];
    int end = g_off[gw + 1];                      // = off + pdeg (multiple of 4)
    for (; j + 8 <= end; j += 8) {
        int4 i0 = *reinterpret_cast<const int4*>(&g_csr[j]);
        int4 i1 = *reinterpret_cast<const int4*>(&g_csr[j + 4]);
        float2 v0 = a2[i0.x * 32 + lane];
        float2 v1 = a2[i0.y * 32 + lane];
        float2 v2 = a2[i0.z * 32 + lane];
        float2 v3 = a2[i0.w * 32 + lane];
        float2 v4 = a2[i1.x * 32 + lane];
        float2 v5 = a2[i1.y * 32 + lane];
        float2 v6 = a2[i1.z * 32 + lane];
        float2 v7 = a2[i1.w * 32 + lane];
        acc.x  += (v0.x + v1.x) + (v2.x + v3.x);
        acc.y  += (v0.y + v1.y) + (v2.y + v3.y);
        acc2.x += (v4.x + v5.x) + (v6.x + v7.x);
        acc2.y += (v4.y + v5.y) + (v6.y + v7.y);
    }
    if (j < end) {                                // remainder is exactly 4
        int4 i0 = *reinterpret_cast<const int4*>(&g_csr[j]);
        float2 v0 = a2[i0.x * 32 + lane];
        float2 v1 = a2[i0.y * 32 + lane];
        float2 v2 = a2[i0.z * 32 + lane];
        float2 v3 = a2[i0.w * 32 + lane];
        acc.x += (v0.x + v1.x) + (v2.x + v3.x);
        acc.y += (v0.y + v1.y) + (v2.y + v3.y);
    }
    acc.x += acc2.x;
    acc.y += acc2.y;
    float d = g_dis[gw];
    reinterpret_cast<float2*>(g_b)[gw * 32 + lane] = make_float2(acc.x * d, acc.y * d);
}

// ---------------------------------------- layer-2 GEMM: elu(g_b+b1) @ W2
__global__ void k_gcn_gemm64(const float* __restrict__ bias,
                             const float* __restrict__ W, int n) {
    __shared__ float As[32][HID];
    __shared__ float Ws[HID * HID];
    int tid = threadIdx.x;
    int row0 = blockIdx.x * 32;

    for (int i = tid; i < HID * HID; i += 256) Ws[i] = W[i];
    for (int i = tid; i < 32 * HID; i += 256) {
        int r = i >> 6, k = i & 63;
        int row = row0 + r;
        As[r][k] = (row < n) ? eluf(g_b[row * HID + k] + bias[k]) : 0.f;
    }
    __syncthreads();

    int fx = (tid & 15) * 4;
    int n0 = (tid >> 4) * 2;
    float4 a0c = make_float4(0.f, 0.f, 0.f, 0.f);
    float4 a1c = make_float4(0.f, 0.f, 0.f, 0.f);
#pragma unroll 16
    for (int k = 0; k < HID; k++) {
        float4 w = *reinterpret_cast<const float4*>(&Ws[k * HID + fx]);
        float a0 = As[n0][k], a1 = As[n0 + 1][k];
        a0c.x += a0 * w.x; a0c.y += a0 * w.y; a0c.z += a0 * w.z; a0c.w += a0 * w.w;
        a1c.x += a1 * w.x; a1c.y += a1 * w.y; a1c.z += a1 * w.z; a1c.w += a1 * w.w;
    }
#pragma unroll
    for (int r = 0; r < 2; r++) {
        int row = row0 + n0 + r;
        if (row >= n) continue;
        float d = g_dis[row];
        float4 acc = r ? a1c : a0c;
        *reinterpret_cast<float4*>(&g_a[row * HID + fx]) =
            make_float4(acc.x * d, acc.y * d, acc.z * d, acc.w * d);
    }
}

// ---------------- fused MLP: elu(elu(g_b+b2)@Wm1+bm1) @ Wm2 + bm2, softmax
__global__ void k_mlp(const float* __restrict__ b2,
                      const float* __restrict__ Wm1,
                      const float* __restrict__ bm1,
                      const float* __restrict__ Wm2,
                      const float* __restrict__ bm2,
                      float* __restrict__ out, int n) {
    __shared__ float As[16][HID];
    __shared__ float Ws[HID * MHID];
    __shared__ float Hs[16][MHID];
    __shared__ float W2s[MHID * KOUT];
    __shared__ float b2s[KOUT];
    int tid = threadIdx.x;
    int row0 = blockIdx.x * 16;

    for (int i = tid; i < HID * MHID; i += 256) Ws[i] = Wm1[i];
    for (int i = tid; i < MHID * KOUT; i += 256) W2s[i] = Wm2[i];
    if (tid < KOUT) b2s[tid] = bm2[tid];
    for (int i = tid; i < 16 * HID; i += 256) {
        int r = i >> 6, k = i & 63;
        int row = row0 + r;
        As[r][k] = (row < n) ? eluf(g_b[row * HID + k] + b2[k]) : 0.f;
    }
    __syncthreads();

    // stage 1: hidden = elu(As @ Wm1 + bm1) -> Hs
    {
        int fx = (tid & 31) * 4;
        int n0 = (tid >> 5) * 2;
        float4 a0c = make_float4(0.f, 0.f, 0.f, 0.f);
        float4 a1c = make_float4(0.f, 0.f, 0.f, 0.f);
#pragma unroll 16
        for (int k = 0; k < HID; k++) {
            float4 w = *reinterpret_cast<const float4*>(&Ws[k * MHID + fx]);
            float a0 = As[n0][k], a1 = As[n0 + 1][k];
            a0c.x += a0 * w.x; a0c.y += a0 * w.y; a0c.z += a0 * w.z; a0c.w += a0 * w.w;
            a1c.x += a1 * w.x; a1c.y += a1 * w.y; a1c.z += a1 * w.z; a1c.w += a1 * w.w;
        }
        float4 bb = *reinterpret_cast<const float4*>(&bm1[fx]);
        *reinterpret_cast<float4*>(&Hs[n0][fx]) =
            make_float4(eluf(a0c.x + bb.x), eluf(a0c.y + bb.y),
                        eluf(a0c.z + bb.z), eluf(a0c.w + bb.w));
        *reinterpret_cast<float4*>(&Hs[n0 + 1][fx]) =
            make_float4(eluf(a1c.x + bb.x), eluf(a1c.y + bb.y),
                        eluf(a1c.z + bb.z), eluf(a1c.w + bb.w));
    }
    __syncthreads();

    // stage 2: warp per 2 rows; logits + softmax
    int wid = tid >> 5;
    int lane = tid & 31;
#pragma unroll
    for (int rr = 0; rr < 2; rr++) {
        int r = wid * 2 + rr;
        int row = row0 + r;
        float p[KOUT];
#pragma unroll
        for (int c = 0; c < KOUT; c++) p[c] = 0.f;
#pragma unroll
        for (int jj = 0; jj < 4; jj++) {
            int k = lane + 32 * jj;
            float hv = Hs[r][k];
#pragma unroll
            for (int c = 0; c < KOUT; c++) p[c] += hv * W2s[k * KOUT + c];
        }
#pragma unroll
        for (int off = 16; off > 0; off >>= 1)
#pragma unroll
            for (int c = 0; c < KOUT; c++)
                p[c] += __shfl_xor_sync(0xffffffffu, p[c], off);

        float mx = -1e30f;
#pragma unroll
        for (int c = 0; c < KOUT; c++) { p[c] += b2s[c]; mx = fmaxf(mx, p[c]); }
        float s = 0.f;
#pragma unroll
        for (int c = 0; c < KOUT; c++) { p[c] = expf(p[c] - mx); s += p[c]; }
        float inv = 1.f / s;
        if (row < n && lane < KOUT) out[row * KOUT + lane] = p[lane] * inv;
    }
}

// ---------------------------------------------------------------- launch
extern "C" void kernel_launch(void* const* d_in, const int* in_sizes, int n_in,
                              void* d_out, int out_size) {
    const float* x   = (const float*)d_in[0];
    const int*   ei  = (const int*)  d_in[1];
    const float* W1  = (const float*)d_in[2];
    const float* b1  = (const float*)d_in[3];
    const float* W2  = (const float*)d_in[4];
    const float* b2  = (const float*)d_in[5];
    const float* Wm1 = (const float*)d_in[6];
    const float* bm1 = (const float*)d_in[7];
    const float* Wm2 = (const float*)d_in[8];
    const float* bm2 = (const float*)d_in[9];
    float* out = (float*)d_out;

    int n = in_sizes[0] / 3;
    int E = in_sizes[1] / 2;
    int nb = (n + SCAN_BS - 1) / SCAN_BS;
    int E4 = E >> 2;
    int degThreads = E4 + (E - E4 * 4);

    // CSR build (rows padded to multiples of 4)
    k_deg_init<<<(n + 255) / 256, 256>>>(n);
    k_deg_edge<<<(degThreads + 255) / 256, 256>>>(ei, E);
    k_scan1<<<nb, SCAN_BS>>>(n);
    k_scan2<<<1, 128>>>(nb, n);
    k_scan3<<<(n + 255) / 256, 256>>>(n);
    k_scatter<<<(degThreads + 255) / 256, 256>>>(ei, E);

    // layer 1
    k_hw1<<<((n + 1) * HID + 255) / 256, 256>>>(x, W1, n);
    int aggr_blocks = (n * 32 + 255) / 256;
    k_aggr<<<aggr_blocks, 256>>>(n);

    // layer 2
    k_gcn_gemm64<<<(n + 31) / 32, 256>>>(b1, W2, n);
    k_aggr<<<aggr_blocks, 256>>>(n);

    // fused MLP + softmax
    k_mlp<<<(n + 15) / 16, 256>>>(b2, Wm1, bm1, Wm2, bm2, out, n);
}

// round 4
// speedup vs baseline: 2.3924x; 1.0652x over previous
#include <cuda_runtime.h>
#include <cuda_fp16.h>
#include <math.h>

#define NMAX 100000
#define EMAX 3200000
#define CSRMAX (EMAX + 3 * NMAX + 8)
#define HID  64
#define MHID 128
#define KOUT 15
#define SCAN_BS 1024

// ---- device-global scratch (no allocations allowed) ----
__device__ __half g_ah[(NMAX + 1) * HID];  // fp16 pre-scaled messages; row n = zeros
__device__ float  g_b[NMAX * HID];         // aggregated output / GEMM input (fp32)
__device__ float  g_dis[NMAX];             // (deg+1)^{-1/2}
__device__ int    g_deg[NMAX];
__device__ int    g_off[NMAX + 1];         // CSR row offsets (padded to x4)
__device__ int    g_cur[NMAX];
__device__ int    g_csr[CSRMAX];           // CSR src indices (padded with n)
__device__ int    g_bsum[(NMAX + SCAN_BS - 1) / SCAN_BS];
__device__ int    g_boff[(NMAX + SCAN_BS - 1) / SCAN_BS];

__device__ __forceinline__ float eluf(float v) { return v > 0.f ? v : expm1f(v); }

// ---------------------------------------------------------------- degrees
__global__ void k_deg_init(int n) {
    int i = blockIdx.x * blockDim.x + threadIdx.x;
    if (i < n) g_deg[i] = 0;
}
__global__ void k_deg_edge(const int* __restrict__ ei, int E) {
    int t = blockIdx.x * blockDim.x + threadIdx.x;
    int E4 = E >> 2;
    if (t < E4) {
        int4 d = reinterpret_cast<const int4*>(ei + E)[t];
        atomicAdd(&g_deg[d.x], 1);
        atomicAdd(&g_deg[d.y], 1);
        atomicAdd(&g_deg[d.z], 1);
        atomicAdd(&g_deg[d.w], 1);
    } else {
        int e = E4 * 4 + (t - E4);
        if (e < E) atomicAdd(&g_deg[ei[E + e]], 1);
    }
}

// ----------------------------------------------------- exclusive scan (3x)
__global__ void k_scan1(int n) {
    __shared__ int s[SCAN_BS];
    int t = threadIdx.x;
    int i = blockIdx.x * SCAN_BS + t;
    int v = (i < n) ? ((g_deg[i] + 3) & ~3) : 0;
    s[t] = v;
    __syncthreads();
#pragma unroll
    for (int off = 1; off < SCAN_BS; off <<= 1) {
        int add = (t >= off) ? s[t - off] : 0;
        __syncthreads();
        s[t] += add;
        __syncthreads();
    }
    if (i < n) g_off[i] = s[t] - v;
    if (t == SCAN_BS - 1) g_bsum[blockIdx.x] = s[t];
}
__global__ void k_scan2(int nb, int n) {
    __shared__ int s[128];
    int t = threadIdx.x;
    int v = (t < nb) ? g_bsum[t] : 0;
    s[t] = v;
    __syncthreads();
#pragma unroll
    for (int off = 1; off < 128; off <<= 1) {
        int add = (t >= off) ? s[t - off] : 0;
        __syncthreads();
        s[t] += add;
        __syncthreads();
    }
    if (t < nb) g_boff[t] = s[t] - v;
    if (t == 127) g_off[n] = s[127];
}
__global__ void k_scan3(int n) {
    int i = blockIdx.x * blockDim.x + threadIdx.x;
    if (i >= n) return;
    int off = g_off[i] + g_boff[i >> 10];
    g_off[i] = off;
    g_cur[i] = off;
    int deg = g_deg[i];
    g_dis[i] = rsqrtf((float)(deg + 1));
    int pdeg = (deg + 3) & ~3;
    for (int j = deg; j < pdeg; j++) g_csr[off + j] = n;   // dummy -> zero row
}

// -------------------------------------------------------------- scatter
__global__ void k_scatter(const int* __restrict__ ei, int E) {
    int t = blockIdx.x * blockDim.x + threadIdx.x;
    int E4 = E >> 2;
    if (t < E4) {
        int4 s = reinterpret_cast<const int4*>(ei)[t];
        int4 d = reinterpret_cast<const int4*>(ei + E)[t];
        g_csr[atomicAdd(&g_cur[d.x], 1)] = s.x;
        g_csr[atomicAdd(&g_cur[d.y], 1)] = s.y;
        g_csr[atomicAdd(&g_cur[d.z], 1)] = s.z;
        g_csr[atomicAdd(&g_cur[d.w], 1)] = s.w;
    } else {
        int e = E4 * 4 + (t - E4);
        if (e < E) g_csr[atomicAdd(&g_cur[ei[E + e]], 1)] = ei[e];
    }
}

// ------------------------------------------- layer-1 input GEMM (3 -> 64)
// thread per 2 features; writes fp16 pre-scaled message pairs
__global__ void k_hw1(const float* __restrict__ x, const float* __restrict__ W1, int n) {
    int idx = blockIdx.x * blockDim.x + threadIdx.x;   // over (n+1)*32
    if (idx >= (n + 1) * 32) return;
    int i = idx >> 5, f = (idx & 31) * 2;
    __half2* a2 = reinterpret_cast<__half2*>(g_ah);
    if (i == n) { a2[idx] = __floats2half2_rn(0.f, 0.f); return; }
    float x0 = x[i * 3 + 0], x1 = x[i * 3 + 1], x2 = x[i * 3 + 2];
    float d = g_dis[i];
    float v0 = (x0 * W1[f]     + x1 * W1[HID + f]     + x2 * W1[2 * HID + f]) * d;
    float v1 = (x0 * W1[f + 1] + x1 * W1[HID + f + 1] + x2 * W1[2 * HID + f + 1]) * d;
    a2[idx] = __floats2half2_rn(v0, v1);
}

// --------------------------------------------- CSR aggregation (hot, x2)
// warp per node; lane holds 2 features (half2 = 4B, warp gathers one 128B line)
__global__ void k_aggr(int n) {
    int gw = (blockIdx.x * blockDim.x + threadIdx.x) >> 5;
    if (gw >= n) return;
    int lane = threadIdx.x & 31;
    const __half2* __restrict__ a2 = reinterpret_cast<const __half2*>(g_ah);

    float2 self = __half22float2(a2[gw * 32 + lane]);
    float accx = self.x, accy = self.y;
    float bccx = 0.f, bccy = 0.f;
    int j = g_off[gw];
    int end = g_off[gw + 1];                      // multiple of 4 past j
    for (; j + 8 <= end; j += 8) {
        int4 i0 = *reinterpret_cast<const int4*>(&g_csr[j]);
        int4 i1 = *reinterpret_cast<const int4*>(&g_csr[j + 4]);
        float2 v0 = __half22float2(a2[i0.x * 32 + lane]);
        float2 v1 = __half22float2(a2[i0.y * 32 + lane]);
        float2 v2 = __half22float2(a2[i0.z * 32 + lane]);
        float2 v3 = __half22float2(a2[i0.w * 32 + lane]);
        float2 v4 = __half22float2(a2[i1.x * 32 + lane]);
        float2 v5 = __half22float2(a2[i1.y * 32 + lane]);
        float2 v6 = __half22float2(a2[i1.z * 32 + lane]);
        float2 v7 = __half22float2(a2[i1.w * 32 + lane]);
        accx += (v0.x + v1.x) + (v2.x + v3.x);
        accy += (v0.y + v1.y) + (v2.y + v3.y);
        bccx += (v4.x + v5.x) + (v6.x + v7.x);
        bccy += (v4.y + v5.y) + (v6.y + v7.y);
    }
    if (j < end) {                                // remainder exactly 4
        int4 i0 = *reinterpret_cast<const int4*>(&g_csr[j]);
        float2 v0 = __half22float2(a2[i0.x * 32 + lane]);
        float2 v1 = __half22float2(a2[i0.y * 32 + lane]);
        float2 v2 = __half22float2(a2[i0.z * 32 + lane]);
        float2 v3 = __half22float2(a2[i0.w * 32 + lane]);
        accx += (v0.x + v1.x) + (v2.x + v3.x);
        accy += (v0.y + v1.y) + (v2.y + v3.y);
    }
    accx += bccx;
    accy += bccy;
    float d = g_dis[gw];
    reinterpret_cast<float2*>(g_b)[gw * 32 + lane] = make_float2(accx * d, accy * d);
}

// ---------------------------------------- layer-2 GEMM: elu(g_b+b1) @ W2
// epilogue writes fp16 pre-scaled messages
__global__ void k_gcn_gemm64(const float* __restrict__ bias,
                             const float* __restrict__ W, int n) {
    __shared__ float As[32][HID];
    __shared__ float Ws[HID * HID];
    int tid = threadIdx.x;
    int row0 = blockIdx.x * 32;

    for (int i = tid; i < HID * HID; i += 256) Ws[i] = W[i];
    for (int i = tid; i < 32 * HID; i += 256) {
        int r = i >> 6, k = i & 63;
        int row = row0 + r;
        As[r][k] = (row < n) ? eluf(g_b[row * HID + k] + bias[k]) : 0.f;
    }
    __syncthreads();

    int fx = (tid & 15) * 4;
    int n0 = (tid >> 4) * 2;
    float4 a0c = make_float4(0.f, 0.f, 0.f, 0.f);
    float4 a1c = make_float4(0.f, 0.f, 0.f, 0.f);
#pragma unroll 16
    for (int k = 0; k < HID; k++) {
        float4 w = *reinterpret_cast<const float4*>(&Ws[k * HID + fx]);
        float a0 = As[n0][k], a1 = As[n0 + 1][k];
        a0c.x += a0 * w.x; a0c.y += a0 * w.y; a0c.z += a0 * w.z; a0c.w += a0 * w.w;
        a1c.x += a1 * w.x; a1c.y += a1 * w.y; a1c.z += a1 * w.z; a1c.w += a1 * w.w;
    }
#pragma unroll
    for (int r = 0; r < 2; r++) {
        int row = row0 + n0 + r;
        if (row >= n) continue;
        float d = g_dis[row];
        float4 acc = r ? a1c : a0c;
        __half2* a2 = reinterpret_cast<__half2*>(g_ah);
        a2[row * 32 + (fx >> 1)]     = __floats2half2_rn(acc.x * d, acc.y * d);
        a2[row * 32 + (fx >> 1) + 1] = __floats2half2_rn(acc.z * d, acc.w * d);
    }
}

// ---------------- fused MLP: elu(elu(g_b+b2)@Wm1+bm1) @ Wm2 + bm2, softmax
__global__ void k_mlp(const float* __restrict__ b2,
                      const float* __restrict__ Wm1,
                      const float* __restrict__ bm1,
                      const float* __restrict__ Wm2,
                      const float* __restrict__ bm2,
                      float* __restrict__ out, int n) {
    __shared__ float As[16][HID];
    __shared__ float Ws[HID * MHID];
    __shared__ float Hs[16][MHID];
    __shared__ float W2s[MHID * KOUT];
    __shared__ float b2s[KOUT];
    int tid = threadIdx.x;
    int row0 = blockIdx.x * 16;

    for (int i = tid; i < HID * MHID; i += 256) Ws[i] = Wm1[i];
    for (int i = tid; i < MHID * KOUT; i += 256) W2s[i] = Wm2[i];
    if (tid < KOUT) b2s[tid] = bm2[tid];
    for (int i = tid; i < 16 * HID; i += 256) {
        int r = i >> 6, k = i & 63;
        int row = row0 + r;
        As[r][k] = (row < n) ? eluf(g_b[row * HID + k] + b2[k]) : 0.f;
    }
    __syncthreads();

    {
        int fx = (tid & 31) * 4;
        int n0 = (tid >> 5) * 2;
        float4 a0c = make_float4(0.f, 0.f, 0.f, 0.f);
        float4 a1c = make_float4(0.f, 0.f, 0.f, 0.f);
#pragma unroll 16
        for (int k = 0; k < HID; k++) {
            float4 w = *reinterpret_cast<const float4*>(&Ws[k * MHID + fx]);
            float a0 = As[n0][k], a1 = As[n0 + 1][k];
            a0c.x += a0 * w.x; a0c.y += a0 * w.y; a0c.z += a0 * w.z; a0c.w += a0 * w.w;
            a1c.x += a1 * w.x; a1c.y += a1 * w.y; a1c.z += a1 * w.z; a1c.w += a1 * w.w;
        }
        float4 bb = *reinterpret_cast<const float4*>(&bm1[fx]);
        *reinterpret_cast<float4*>(&Hs[n0][fx]) =
            make_float4(eluf(a0c.x + bb.x), eluf(a0c.y + bb.y),
                        eluf(a0c.z + bb.z), eluf(a0c.w + bb.w));
        *reinterpret_cast<float4*>(&Hs[n0 + 1][fx]) =
            make_float4(eluf(a1c.x + bb.x), eluf(a1c.y + bb.y),
                        eluf(a1c.z + bb.z), eluf(a1c.w + bb.w));
    }
    __syncthreads();

    int wid = tid >> 5;
    int lane = tid & 31;
#pragma unroll
    for (int rr = 0; rr < 2; rr++) {
        int r = wid * 2 + rr;
        int row = row0 + r;
        float p[KOUT];
#pragma unroll
        for (int c = 0; c < KOUT; c++) p[c] = 0.f;
#pragma unroll
        for (int jj = 0; jj < 4; jj++) {
            int k = lane + 32 * jj;
            float hv = Hs[r][k];
#pragma unroll
            for (int c = 0; c < KOUT; c++) p[c] += hv * W2s[k * KOUT + c];
        }
#pragma unroll
        for (int off = 16; off > 0; off >>= 1)
#pragma unroll
            for (int c = 0; c < KOUT; c++)
                p[c] += __shfl_xor_sync(0xffffffffu, p[c], off);

        float mx = -1e30f;
#pragma unroll
        for (int c = 0; c < KOUT; c++) { p[c] += b2s[c]; mx = fmaxf(mx, p[c]); }
        float s = 0.f;
#pragma unroll
        for (int c = 0; c < KOUT; c++) { p[c] = expf(p[c] - mx); s += p[c]; }
        float inv = 1.f / s;
        if (row < n && lane < KOUT) out[row * KOUT + lane] = p[lane] * inv;
    }
}

// ---------------------------------------------------------------- launch
extern "C" void kernel_launch(void* const* d_in, const int* in_sizes, int n_in,
                              void* d_out, int out_size) {
    const float* x   = (const float*)d_in[0];
    const int*   ei  = (const int*)  d_in[1];
    const float* W1  = (const float*)d_in[2];
    const float* b1  = (const float*)d_in[3];
    const float* W2  = (const float*)d_in[4];
    const float* b2  = (const float*)d_in[5];
    const float* Wm1 = (const float*)d_in[6];
    const float* bm1 = (const float*)d_in[7];
    const float* Wm2 = (const float*)d_in[8];
    const float* bm2 = (const float*)d_in[9];
    float* out = (float*)d_out;

    int n = in_sizes[0] / 3;
    int E = in_sizes[1] / 2;
    int nb = (n + SCAN_BS - 1) / SCAN_BS;
    int E4 = E >> 2;
    int degThreads = E4 + (E - E4 * 4);

    // CSR build
    k_deg_init<<<(n + 255) / 256, 256>>>(n);
    k_deg_edge<<<(degThreads + 255) / 256, 256>>>(ei, E);
    k_scan1<<<nb, SCAN_BS>>>(n);
    k_scan2<<<1, 128>>>(nb, n);
    k_scan3<<<(n + 255) / 256, 256>>>(n);
    k_scatter<<<(degThreads + 255) / 256, 256>>>(ei, E);

    // layer 1
    k_hw1<<<((n + 1) * 32 + 255) / 256, 256>>>(x, W1, n);
    int aggr_blocks = (n * 32 + 255) / 256;
    k_aggr<<<aggr_blocks, 256>>>(n);

    // layer 2
    k_gcn_gemm64<<<(n + 31) / 32, 256>>>(b1, W2, n);
    k_aggr<<<aggr_blocks, 256>>>(n);

    // fused MLP + softmax
    k_mlp<<<(n + 15) / 16, 256>>>(b2, Wm1, bm1, Wm2, bm2, out, n);
}